// round 4
// baseline (speedup 1.0000x reference)
#include <cuda_runtime.h>
#include <math.h>

#define NB 2048
#define NC 100
#define NK 8
#define ND 64
#define NCK 800
#define CKP 832
#define NPAIR 2080
#define PDIM 2145
#define PPAD 2176

typedef unsigned long long u64;

__device__ __align__(128) float g_At[PPAD * CKP];
__device__ __align__(128) float g_Gt[PPAD * NB];
__device__ __align__(128) float g_cls[NB * NC];

// ---- Kernel 1: per-(c,k) prep: invert L, build packed A / linear / const rows
__global__ void prep_kernel(const float* __restrict__ mix,
                            const float* __restrict__ loc,
                            const float* __restrict__ tril) {
    const int ck = blockIdx.x, tid = threadIdx.x;
    if (ck >= NCK) {
        for (int p = tid; p < PPAD; p += 64) g_At[p * CKP + ck] = 0.0f;
        return;
    }
    const int c = ck >> 3, k = ck & 7;
    __shared__ float Lsh[ND][65];
    __shared__ float rowbuf[ND], locsh[ND], vsh[ND], red[ND];
    __shared__ int rs[ND + 1];

    const float* Lg = tril + (size_t)ck * ND * ND;
    for (int idx = tid; idx < ND * ND; idx += 64) Lsh[idx >> 6][idx & 63] = Lg[idx];
    locsh[tid] = loc[ck * ND + tid];
    rs[tid] = tid * ND - tid * (tid - 1) / 2;
    if (tid == 0) rs[ND] = NPAIR;
    __syncthreads();
    const float mydiag = Lsh[tid][tid];

    // in-place forward substitution: rows become M = L^{-1}
    for (int i = 0; i < ND; ++i) {
        rowbuf[tid] = Lsh[i][tid];
        __syncthreads();
        float nv = 0.0f;
        if (tid <= i) {
            float s = (tid == i) ? 1.0f : 0.0f;
            for (int t = tid; t < i; ++t) s -= rowbuf[t] * Lsh[t][tid];
            nv = s / rowbuf[i];
        }
        Lsh[i][tid] = nv;
        __syncthreads();
    }

    float vd = 0.0f;                                  // v = M*mu
    for (int t = 0; t <= tid; ++t) vd += Lsh[tid][t] * locsh[t];
    vsh[tid] = vd;
    __syncthreads();
    float wd = 0.0f;                                  // w = M^T v = A*mu
    for (int t = tid; t < ND; ++t) wd += Lsh[t][tid] * vsh[t];
    g_At[(NPAIR + tid) * CKP + ck] = -2.0f * wd;

    red[tid] = vd * vd;  __syncthreads();
    for (int o = 32; o > 0; o >>= 1) { if (tid < o) red[tid] += red[tid + o]; __syncthreads(); }
    const float cst = red[0];  __syncthreads();
    red[tid] = logf(fabsf(mydiag));  __syncthreads();
    for (int o = 32; o > 0; o >>= 1) { if (tid < o) red[tid] += red[tid + o]; __syncthreads(); }
    const float logdet = red[0];

    float ml[NK], mmx = -1e30f;
    #pragma unroll
    for (int kk = 0; kk < NK; ++kk) { ml[kk] = mix[c * NK + kk]; mmx = fmaxf(mmx, ml[kk]); }
    float msum = 0.0f;
    #pragma unroll
    for (int kk = 0; kk < NK; ++kk) msum += expf(ml[kk] - mmx);
    const float mixlog = ml[k] - (mmx + logf(msum));
    const float bias = -0.5f * cst - 32.0f * 1.8378770664093454836f - logdet + mixlog;
    if (tid == 0) g_At[2144 * CKP + ck] = -2.0f * bias;
    for (int p = PDIM + tid; p < PPAD; p += 64) g_At[p * CKP + ck] = 0.0f;

    int i = 0;                                        // packed A = M^T M
    for (int p = tid; p < NPAIR; p += 64) {
        while (rs[i + 1] <= p) ++i;
        const int j = i + (p - rs[i]);
        float s = 0.0f;
        for (int t = j; t < ND; ++t) s += Lsh[t][i] * Lsh[t][j];
        g_At[p * CKP + ck] = (i == j) ? s : 2.0f * s;
    }
}

// ---- Kernel 2: G^T [p][b]: x_i*x_j rows, x_d rows, const row, zero pad
__global__ void gbuild_kernel(const float* __restrict__ rep) {
    __shared__ float xs[ND * 129];
    const int bt = blockIdx.x, i = blockIdx.y, tid = threadIdx.x;
    for (int f = tid; f < 128 * ND; f += 128) {
        const int b = f >> 6, d = f & 63;
        xs[d * 129 + b] = rep[(bt * 128 + b) * ND + d];
    }
    __syncthreads();
    const int b = bt * 128 + tid;
    const int rsI = i * ND - i * (i - 1) / 2;
    const float xi = xs[i * 129 + tid];
    for (int j = i; j < ND; ++j)
        g_Gt[(rsI + j - i) * NB + b] = xi * xs[j * 129 + tid];
    if (i == 0) {
        #pragma unroll 4
        for (int d = 0; d < ND; ++d) g_Gt[(NPAIR + d) * NB + b] = xs[d * 129 + tid];
        g_Gt[2144 * NB + b] = 1.0f;
        for (int p = PDIM; p < PPAD; ++p) g_Gt[p * NB + b] = 0.0f;
    }
}

// ---- Kernel 3: fp32 GEMM via packed fma.rn.f32x2 (FFMA2) + fused lse over k
#define BM 64
#define BN 64
#define KS 16
#define NSLICE (PPAD / KS)

__device__ __forceinline__ void cp16(float* s, const float* g) {
    unsigned a = (unsigned)__cvta_generic_to_shared(s);
    asm volatile("cp.async.cg.shared.global [%0], [%1], 16;\n" :: "r"(a), "l"(g));
}
__device__ __forceinline__ u64 bcast2(float v) {
    u64 r; asm("mov.b64 %0, {%1, %1};" : "=l"(r) : "f"(v)); return r;
}
__device__ __forceinline__ void ffma2(u64& d, u64 a, u64 b) {
    asm("fma.rn.f32x2 %0, %1, %2, %0;" : "+l"(d) : "l"(a), "l"(b));
}
__device__ __forceinline__ void unpack2(u64 v, float& lo, float& hi) {
    asm("mov.b64 {%0, %1}, %2;" : "=f"(lo), "=f"(hi) : "l"(v));
}

__global__ void __launch_bounds__(128) gemm_kernel() {
    __shared__ __align__(16) float Gs[2][KS][BM];
    __shared__ __align__(16) float As[2][KS][BN];
    const int tid = threadIdx.x;
    const int bm0 = blockIdx.x * BM, bn0 = blockIdx.y * BN;
    const int tx = tid & 15, ty = tid >> 4;

    u64 acc[4][4];   // [m-pair][n] : lane0 = m even, lane1 = m odd
    #pragma unroll
    for (int m = 0; m < 4; ++m)
        #pragma unroll
        for (int n = 0; n < 4; ++n) acc[m][n] = 0ull;

    #pragma unroll
    for (int q = 0; q < 2; ++q) {
        const int f = tid + 128 * q, r = f >> 4, cc = (f & 15) * 4;
        cp16(&Gs[0][r][cc], g_Gt + r * NB + bm0 + cc);
        cp16(&As[0][r][cc], g_At + r * CKP + bn0 + cc);
    }
    asm volatile("cp.async.commit_group;\n" ::: "memory");

    for (int s = 0; s < NSLICE; ++s) {
        const int buf = s & 1;
        if (s + 1 < NSLICE) {
            const int p0 = (s + 1) * KS, nb = buf ^ 1;
            #pragma unroll
            for (int q = 0; q < 2; ++q) {
                const int f = tid + 128 * q, r = f >> 4, cc = (f & 15) * 4;
                cp16(&Gs[nb][r][cc], g_Gt + (p0 + r) * NB + bm0 + cc);
                cp16(&As[nb][r][cc], g_At + (p0 + r) * CKP + bn0 + cc);
            }
            asm volatile("cp.async.commit_group;\n" ::: "memory");
            asm volatile("cp.async.wait_group 1;\n" ::: "memory");
        } else {
            asm volatile("cp.async.wait_group 0;\n" ::: "memory");
        }
        __syncthreads();
        #pragma unroll
        for (int kk = 0; kk < KS; ++kk) {
            const u64* gp = reinterpret_cast<const u64*>(&Gs[buf][kk][ty * 8]);
            const u64 g0 = gp[0], g1 = gp[1], g2 = gp[2], g3 = gp[3];
            const float4 aa = *reinterpret_cast<const float4*>(&As[buf][kk][tx * 4]);
            const u64 a0 = bcast2(aa.x), a1 = bcast2(aa.y);
            const u64 a2 = bcast2(aa.z), a3 = bcast2(aa.w);
            ffma2(acc[0][0], g0, a0); ffma2(acc[0][1], g0, a1);
            ffma2(acc[0][2], g0, a2); ffma2(acc[0][3], g0, a3);
            ffma2(acc[1][0], g1, a0); ffma2(acc[1][1], g1, a1);
            ffma2(acc[1][2], g1, a2); ffma2(acc[1][3], g1, a3);
            ffma2(acc[2][0], g2, a0); ffma2(acc[2][1], g2, a1);
            ffma2(acc[2][2], g2, a2); ffma2(acc[2][3], g2, a3);
            ffma2(acc[3][0], g3, a0); ffma2(acc[3][1], g3, a1);
            ffma2(acc[3][2], g3, a2); ffma2(acc[3][3], g3, a3);
        }
        __syncthreads();
    }

    // unpack to scalar accumulators [8][4]
    float sc[8][4];
    #pragma unroll
    for (int mp = 0; mp < 4; ++mp)
        #pragma unroll
        for (int n = 0; n < 4; ++n)
            unpack2(acc[mp][n], sc[2 * mp][n], sc[2 * mp + 1][n]);

    const int c = bn0 / 8 + (tx >> 1);
    const bool store = ((tx & 1) == 0) && (c < NC);
    #pragma unroll
    for (int m = 0; m < 8; ++m) {
        const float s0 = -0.5f * sc[m][0], s1 = -0.5f * sc[m][1];
        const float s2 = -0.5f * sc[m][2], s3 = -0.5f * sc[m][3];
        float mx = fmaxf(fmaxf(s0, s1), fmaxf(s2, s3));
        float se = expf(s0 - mx) + expf(s1 - mx) + expf(s2 - mx) + expf(s3 - mx);
        const float pm = __shfl_xor_sync(0xffffffffu, mx, 1);
        const float ps = __shfl_xor_sync(0xffffffffu, se, 1);
        const float M2 = fmaxf(mx, pm);
        const float tot = se * expf(mx - M2) + ps * expf(pm - M2);
        if (store) g_cls[(bm0 + ty * 8 + m) * NC + c] = M2 + logf(tot);
    }
}

// ---- Kernel 4: row log_softmax over C=100 (one warp per row)
__global__ void softmax_kernel(float* __restrict__ out) {
    const int lane = threadIdx.x & 31;
    const int b = blockIdx.x * 8 + (threadIdx.x >> 5);
    float v[4];
    float mx = -INFINITY;
    #pragma unroll
    for (int q = 0; q < 4; ++q) {
        const int cc = lane + 32 * q;
        v[q] = (cc < NC) ? g_cls[b * NC + cc] : -INFINITY;
        mx = fmaxf(mx, v[q]);
    }
    #pragma unroll
    for (int o = 16; o > 0; o >>= 1) mx = fmaxf(mx, __shfl_xor_sync(0xffffffffu, mx, o));
    float sum = 0.0f;
    #pragma unroll
    for (int q = 0; q < 4; ++q) {
        const int cc = lane + 32 * q;
        if (cc < NC) sum += expf(v[q] - mx);
    }
    #pragma unroll
    for (int o = 16; o > 0; o >>= 1) sum += __shfl_xor_sync(0xffffffffu, sum, o);
    const float lse = mx + logf(sum);
    #pragma unroll
    for (int q = 0; q < 4; ++q) {
        const int cc = lane + 32 * q;
        if (cc < NC) out[b * NC + cc] = v[q] - lse;
    }
}

extern "C" void kernel_launch(void* const* d_in, const int* in_sizes, int n_in,
                              void* d_out, int out_size) {
    const float *rep = nullptr, *mix = nullptr, *loc = nullptr, *tril = nullptr;
    for (int i = 0; i < n_in; ++i) {
        switch (in_sizes[i]) {
            case NB * ND:       rep  = (const float*)d_in[i]; break;
            case NC * NK:       mix  = (const float*)d_in[i]; break;
            case NCK * ND:      loc  = (const float*)d_in[i]; break;
            case NCK * ND * ND: tril = (const float*)d_in[i]; break;
            default: break;
        }
    }
    if (!rep || !mix || !loc || !tril) {   // positional fallback (reference order)
        rep  = (const float*)d_in[0];
        mix  = (const float*)d_in[1];
        loc  = (const float*)d_in[2];
        tril = (const float*)d_in[3];
    }
    prep_kernel<<<CKP, 64>>>(mix, loc, tril);
    gbuild_kernel<<<dim3(NB / 128, ND), 128>>>(rep);
    gemm_kernel<<<dim3(NB / BM, CKP / BN), 128>>>();
    softmax_kernel<<<NB / 8, 256>>>((float*)d_out);
}

// round 6
// speedup vs baseline: 1.7517x; 1.7517x over previous
#include <cuda_runtime.h>
#include <cuda_bf16.h>
#include <cstdint>
#include <math.h>

#define NB 2048
#define NC 100
#define NK 8
#define ND 64
#define NCK 800
#define NPAIR 2080
#define PDIM 2145
#define PPAD 2176
#define KE   (3 * PPAD)        // 6528
#define CK2  896               // ck padded to 7*128
#define BM 128
#define BN 128
#define KSTG 32                // bf16 k per stage
#define NST (KE / KSTG)        // 204
#define SROW 40                // padded smem row (bf16 elems) = 80 B

__device__ __align__(128) __nv_bfloat16 g_G2[(size_t)NB * KE];   // [b][k]
__device__ __align__(128) __nv_bfloat16 g_A2[(size_t)CK2 * KE];  // [ck][k]
__device__ __align__(128) float g_cls[NB * NC];

// ---------------- helpers ----------------
__device__ __forceinline__ uint32_t smem_u32(const void* p) {
    uint32_t a;
    asm("{ .reg .u64 t; cvta.to.shared.u64 t, %1; cvt.u32.u64 %0, t; }" : "=r"(a) : "l"(p));
    return a;
}
__device__ __forceinline__ void cp16(uint32_t saddr, const void* g) {
    asm volatile("cp.async.cg.shared.global [%0], [%1], 16;\n" :: "r"(saddr), "l"(g));
}
#define CP_COMMIT()  asm volatile("cp.async.commit_group;\n" ::: "memory")
#define CP_WAIT(n)   asm volatile("cp.async.wait_group %0;\n" :: "n"(n) : "memory")

__device__ __forceinline__ void ldsm4(uint32_t& r0, uint32_t& r1, uint32_t& r2, uint32_t& r3,
                                      uint32_t addr) {
    asm volatile("ldmatrix.sync.aligned.m8n8.x4.shared.b16 {%0,%1,%2,%3}, [%4];"
                 : "=r"(r0), "=r"(r1), "=r"(r2), "=r"(r3) : "r"(addr));
}
__device__ __forceinline__ void mma16816(float* d, uint32_t a0, uint32_t a1, uint32_t a2,
                                         uint32_t a3, uint32_t b0, uint32_t b1) {
    asm volatile("mma.sync.aligned.m16n8k16.row.col.f32.bf16.bf16.f32 "
                 "{%0,%1,%2,%3}, {%4,%5,%6,%7}, {%8,%9}, {%0,%1,%2,%3};"
                 : "+f"(d[0]), "+f"(d[1]), "+f"(d[2]), "+f"(d[3])
                 : "r"(a0), "r"(a1), "r"(a2), "r"(a3), "r"(b0), "r"(b1));
}

// ---------------- Kernel 1: prep (invert L, packed A rows, hi/lo bf16 split) ----
__device__ __forceinline__ void storeA(int ck, int p, float v) {
    __nv_bfloat16 h = __float2bfloat16(v);
    __nv_bfloat16 l = __float2bfloat16(v - __bfloat162float(h));
    const size_t base = (size_t)ck * KE;
    g_A2[base + p] = h;                 // seg0: ah   (pairs gh)
    g_A2[base + PPAD + p] = h;          // seg1: ah   (pairs gl)
    g_A2[base + 2 * PPAD + p] = l;      // seg2: al   (pairs gh)
}

__global__ void prep_kernel(const float* __restrict__ mix,
                            const float* __restrict__ loc,
                            const float* __restrict__ tril) {
    const int ck = blockIdx.x, tid = threadIdx.x;
    if (ck >= NCK) {
        const size_t base = (size_t)ck * KE;
        for (int p = tid; p < KE; p += 64) g_A2[base + p] = __float2bfloat16(0.0f);
        return;
    }
    const int c = ck >> 3, k = ck & 7;
    __shared__ float Lsh[ND][65];
    __shared__ float rowbuf[ND], locsh[ND], vsh[ND], red[ND];
    __shared__ int rs[ND + 1];

    const float* Lg = tril + (size_t)ck * ND * ND;
    for (int idx = tid; idx < ND * ND; idx += 64) Lsh[idx >> 6][idx & 63] = Lg[idx];
    locsh[tid] = loc[ck * ND + tid];
    rs[tid] = tid * ND - tid * (tid - 1) / 2;
    if (tid == 0) rs[ND] = NPAIR;
    __syncthreads();
    const float mydiag = Lsh[tid][tid];

    for (int i = 0; i < ND; ++i) {          // rows become M = L^{-1}
        rowbuf[tid] = Lsh[i][tid];
        __syncthreads();
        float nv = 0.0f;
        if (tid <= i) {
            float s = (tid == i) ? 1.0f : 0.0f;
            for (int t = tid; t < i; ++t) s -= rowbuf[t] * Lsh[t][tid];
            nv = s / rowbuf[i];
        }
        Lsh[i][tid] = nv;
        __syncthreads();
    }

    float vd = 0.0f;                        // v = M*mu
    for (int t = 0; t <= tid; ++t) vd += Lsh[tid][t] * locsh[t];
    vsh[tid] = vd;
    __syncthreads();
    float wd = 0.0f;                        // w = A*mu
    for (int t = tid; t < ND; ++t) wd += Lsh[t][tid] * vsh[t];
    storeA(ck, NPAIR + tid, -2.0f * wd);

    red[tid] = vd * vd;  __syncthreads();
    for (int o = 32; o > 0; o >>= 1) { if (tid < o) red[tid] += red[tid + o]; __syncthreads(); }
    const float cst = red[0];  __syncthreads();
    red[tid] = logf(fabsf(mydiag));  __syncthreads();
    for (int o = 32; o > 0; o >>= 1) { if (tid < o) red[tid] += red[tid + o]; __syncthreads(); }
    const float logdet = red[0];

    float ml[NK], mmx = -1e30f;
    #pragma unroll
    for (int kk = 0; kk < NK; ++kk) { ml[kk] = mix[c * NK + kk]; mmx = fmaxf(mmx, ml[kk]); }
    float msum = 0.0f;
    #pragma unroll
    for (int kk = 0; kk < NK; ++kk) msum += expf(ml[kk] - mmx);
    const float mixlog = ml[k] - (mmx + logf(msum));
    const float bias = -0.5f * cst - 32.0f * 1.8378770664093454836f - logdet + mixlog;
    if (tid == 0) storeA(ck, 2144, -2.0f * bias);
    for (int p = PDIM + tid; p < PPAD; p += 64) storeA(ck, p, 0.0f);

    int i = 0;                              // packed A = M^T M
    for (int p = tid; p < NPAIR; p += 64) {
        while (rs[i + 1] <= p) ++i;
        const int j = i + (p - rs[i]);
        float s = 0.0f;
        for (int t = j; t < ND; ++t) s += Lsh[t][i] * Lsh[t][j];
        storeA(ck, p, (i == j) ? s : 2.0f * s);
    }
}

// ---------------- Kernel 2: G rows (bf16 hi/lo, [b][k] layout) -------------
__global__ void gbuild_kernel(const float* __restrict__ rep) {
    __shared__ float xs[64 * 65];
    __shared__ int is[64], js[64];
    const int p0 = blockIdx.x * 64, b0 = blockIdx.y * 64;
    const int tid = threadIdx.x, lane = tid & 31, w = tid >> 5;

    for (int f = tid; f < 64 * 64; f += 256) {
        const int bl = f >> 6, d = f & 63;
        xs[bl * 65 + d] = rep[(size_t)(b0 + bl) * ND + d];
    }
    if (tid < 64) {
        const int p = p0 + tid;
        if (p < NPAIR) {
            int i = 0;
            while ((i + 1) * ND - (i + 1) * i / 2 <= p) ++i;
            const int rsI = i * ND - i * (i - 1) / 2;
            is[tid] = i; js[tid] = i + (p - rsI);
        } else if (p < 2144) { is[tid] = -1; js[tid] = p - NPAIR; }
        else if (p == 2144) { is[tid] = -2; js[tid] = 0; }
        else { is[tid] = -3; js[tid] = 0; }
    }
    __syncthreads();

    const int pl = 2 * lane;
    const int i0 = is[pl], j0 = js[pl], i1 = is[pl + 1], j1 = js[pl + 1];
    #pragma unroll 2
    for (int it = 0; it < 8; ++it) {
        const int bl = w + 8 * it;
        const float* xr = &xs[bl * 65];
        float v0 = (i0 >= 0) ? xr[i0] * xr[j0] : (i0 == -1 ? xr[j0] : (i0 == -2 ? 1.0f : 0.0f));
        float v1 = (i1 >= 0) ? xr[i1] * xr[j1] : (i1 == -1 ? xr[j1] : (i1 == -2 ? 1.0f : 0.0f));
        __nv_bfloat16 h0 = __float2bfloat16(v0), h1 = __float2bfloat16(v1);
        __nv_bfloat16 l0 = __float2bfloat16(v0 - __bfloat162float(h0));
        __nv_bfloat16 l1 = __float2bfloat16(v1 - __bfloat162float(h1));
        const size_t base = (size_t)(b0 + bl) * KE + p0 + pl;
        *(__nv_bfloat162*)(g_G2 + base)            = __nv_bfloat162(h0, h1);  // gh
        *(__nv_bfloat162*)(g_G2 + base + PPAD)     = __nv_bfloat162(l0, l1);  // gl
        *(__nv_bfloat162*)(g_G2 + base + 2 * PPAD) = __nv_bfloat162(h0, h1);  // gh
    }
}

// ---------------- Kernel 3: mma.sync bf16 GEMM + fused lse over k ----------
// 256 thr = 8 warps; warp tile 32(m) x 64(n); block 128x128; K-stage 32.
__global__ void __launch_bounds__(256) gemm_kernel() {
    __shared__ __align__(16) __nv_bfloat16 sA[2][BM][SROW];
    __shared__ __align__(16) __nv_bfloat16 sB[2][BN][SROW];
    const int tid = threadIdx.x, lane = tid & 31, wid = tid >> 5;
    const int wm = wid & 3, wn = wid >> 2;             // 4 x 2 warps
    const int bm0 = blockIdx.x * BM, bn0 = blockIdx.y * BN;
    const __nv_bfloat16* gA = g_G2 + (size_t)bm0 * KE;
    const __nv_bfloat16* gB = g_A2 + (size_t)bn0 * KE;
    const uint32_t sA0 = smem_u32(&sA[0][0][0]);
    const uint32_t sB0 = smem_u32(&sB[0][0][0]);
    const uint32_t BUFB = BM * SROW * 2;               // bytes per buffer

    float acc[2][8][4];
    #pragma unroll
    for (int mt = 0; mt < 2; ++mt)
        #pragma unroll
        for (int nt = 0; nt < 8; ++nt)
            #pragma unroll
            for (int e = 0; e < 4; ++e) acc[mt][nt][e] = 0.0f;

    // ldmatrix source addresses (fixed per thread, + buffer/col offsets)
    const int aRow = wm * 32 + (lane & 7) + ((lane >> 3) & 1) * 8;   // + mt*16
    const int aColB = ((lane >> 4) * 8) * 2;                         // byte offset, + h*32
    const int bRow = wn * 64 + (lane & 7) + ((lane >> 4) & 1) * 8;   // + nt2*16
    const int bColB = (((lane >> 3) & 1) * 8) * 2;                   // + h*32

    #define LOAD_STAGE(s, buf) do {                                          \
        const int k0_ = (s) * KSTG;                                          \
        _Pragma("unroll")                                                    \
        for (int q = 0; q < 2; ++q) {                                        \
            const int f = tid + 256 * q;                                     \
            const int r = f >> 2, cc = f & 3;                                \
            cp16(sA0 + (buf) * BUFB + r * (SROW * 2) + cc * 16,              \
                 gA + (size_t)r * KE + k0_ + cc * 8);                        \
            cp16(sB0 + (buf) * BUFB + r * (SROW * 2) + cc * 16,              \
                 gB + (size_t)r * KE + k0_ + cc * 8);                        \
        }                                                                    \
        CP_COMMIT();                                                         \
    } while (0)

    LOAD_STAGE(0, 0);

    #pragma unroll 1
    for (int s = 0; s < NST; ++s) {
        const int buf = s & 1;
        if (s + 1 < NST) { LOAD_STAGE(s + 1, buf ^ 1); CP_WAIT(1); }
        else             { CP_WAIT(0); }
        __syncthreads();

        const uint32_t aBase = sA0 + buf * BUFB;
        const uint32_t bBase = sB0 + buf * BUFB;
        #pragma unroll
        for (int h = 0; h < 2; ++h) {
            uint32_t a[2][4];
            #pragma unroll
            for (int mt = 0; mt < 2; ++mt)
                ldsm4(a[mt][0], a[mt][1], a[mt][2], a[mt][3],
                      aBase + (aRow + mt * 16) * (SROW * 2) + aColB + h * 32);
            uint32_t b[4][4];
            #pragma unroll
            for (int nt2 = 0; nt2 < 4; ++nt2)
                ldsm4(b[nt2][0], b[nt2][1], b[nt2][2], b[nt2][3],
                      bBase + (bRow + nt2 * 16) * (SROW * 2) + bColB + h * 32);
            #pragma unroll
            for (int mt = 0; mt < 2; ++mt)
                #pragma unroll
                for (int nt = 0; nt < 8; ++nt)
                    mma16816(acc[mt][nt], a[mt][0], a[mt][1], a[mt][2], a[mt][3],
                             b[nt >> 1][(nt & 1) * 2], b[nt >> 1][(nt & 1) * 2 + 1]);
        }
        __syncthreads();
    }

    // Epilogue: each n8 tile = one class (8 mixture comps). lse across the
    // 4-lane quad (each thread holds 2 cols), rows groupID and groupID+8.
    const int gID = lane >> 2, tig = lane & 3;
    #pragma unroll
    for (int mt = 0; mt < 2; ++mt) {
        const int row0 = bm0 + wm * 32 + mt * 16 + gID;
        #pragma unroll
        for (int nt = 0; nt < 8; ++nt) {
            const int c = bn0 / 8 + wn * 8 + nt;
            #pragma unroll
            for (int half = 0; half < 2; ++half) {
                const float v0 = -0.5f * acc[mt][nt][2 * half];
                const float v1 = -0.5f * acc[mt][nt][2 * half + 1];
                float m = fmaxf(v0, v1);
                float se = expf(v0 - m) + expf(v1 - m);
                #pragma unroll
                for (int o = 1; o <= 2; o <<= 1) {
                    const float pm = __shfl_xor_sync(0xffffffffu, m, o);
                    const float ps = __shfl_xor_sync(0xffffffffu, se, o);
                    const float M2 = fmaxf(m, pm);
                    se = se * expf(m - M2) + ps * expf(pm - M2);
                    m = M2;
                }
                if (tig == 0 && c < NC)
                    g_cls[(size_t)(row0 + 8 * half) * NC + c] = m + logf(se);
            }
        }
    }
}

// ---------------- Kernel 4: row log_softmax over C=100 ---------------------
__global__ void softmax_kernel(float* __restrict__ out) {
    const int lane = threadIdx.x & 31;
    const int b = blockIdx.x * 8 + (threadIdx.x >> 5);
    float v[4];
    float mx = -INFINITY;
    #pragma unroll
    for (int q = 0; q < 4; ++q) {
        const int cc = lane + 32 * q;
        v[q] = (cc < NC) ? g_cls[b * NC + cc] : -INFINITY;
        mx = fmaxf(mx, v[q]);
    }
    #pragma unroll
    for (int o = 16; o > 0; o >>= 1) mx = fmaxf(mx, __shfl_xor_sync(0xffffffffu, mx, o));
    float sum = 0.0f;
    #pragma unroll
    for (int q = 0; q < 4; ++q) {
        const int cc = lane + 32 * q;
        if (cc < NC) sum += expf(v[q] - mx);
    }
    #pragma unroll
    for (int o = 16; o > 0; o >>= 1) sum += __shfl_xor_sync(0xffffffffu, sum, o);
    const float lse = mx + logf(sum);
    #pragma unroll
    for (int q = 0; q < 4; ++q) {
        const int cc = lane + 32 * q;
        if (cc < NC) out[b * NC + cc] = v[q] - lse;
    }
}

extern "C" void kernel_launch(void* const* d_in, const int* in_sizes, int n_in,
                              void* d_out, int out_size) {
    const float *rep = nullptr, *mix = nullptr, *loc = nullptr, *tril = nullptr;
    for (int i = 0; i < n_in; ++i) {
        switch (in_sizes[i]) {
            case NB * ND:       rep  = (const float*)d_in[i]; break;
            case NC * NK:       mix  = (const float*)d_in[i]; break;
            case NCK * ND:      loc  = (const float*)d_in[i]; break;
            case NCK * ND * ND: tril = (const float*)d_in[i]; break;
            default: break;
        }
    }
    if (!rep || !mix || !loc || !tril) {
        rep  = (const float*)d_in[0];
        mix  = (const float*)d_in[1];
        loc  = (const float*)d_in[2];
        tril = (const float*)d_in[3];
    }
    prep_kernel<<<CK2, 64>>>(mix, loc, tril);
    gbuild_kernel<<<dim3(PPAD / 64, NB / 64), 256>>>(rep);
    gemm_kernel<<<dim3(NB / BM, CK2 / BN), 256>>>();
    softmax_kernel<<<NB / 8, 256>>>((float*)d_out);
}

// round 8
// speedup vs baseline: 1.7933x; 1.0238x over previous
#include <cuda_runtime.h>
#include <cuda_bf16.h>
#include <cstdint>
#include <math.h>

#define NB 2048
#define NC 100
#define NK 8
#define ND 64
#define NCK 800
#define NPAIR 2080
#define PDIM 2145
#define PPAD 2176
#define KE   (3 * PPAD)        // 6528
#define CK2  832               // ck padded to 13*64
#define BM 128
#define BN 64
#define KSTG 32                // bf16 k per stage
#define NST (KE / KSTG)        // 204
#define SROW 40                // padded smem row (bf16 elems) = 80 B

__device__ __align__(128) __nv_bfloat16 g_G2[(size_t)NB * KE];   // [b][k]
__device__ __align__(128) __nv_bfloat16 g_A2[(size_t)CK2 * KE];  // [ck][k]
__device__ __align__(128) float g_cls[NB * NC];

// ---------------- helpers ----------------
__device__ __forceinline__ uint32_t smem_u32(const void* p) {
    uint32_t a;
    asm("{ .reg .u64 t; cvta.to.shared.u64 t, %1; cvt.u32.u64 %0, t; }" : "=r"(a) : "l"(p));
    return a;
}
__device__ __forceinline__ void cp16(uint32_t saddr, const void* g) {
    asm volatile("cp.async.cg.shared.global [%0], [%1], 16;\n" :: "r"(saddr), "l"(g));
}
#define CP_COMMIT()  asm volatile("cp.async.commit_group;\n" ::: "memory")
#define CP_WAIT(n)   asm volatile("cp.async.wait_group %0;\n" :: "n"(n) : "memory")

__device__ __forceinline__ void ldsm4(uint32_t& r0, uint32_t& r1, uint32_t& r2, uint32_t& r3,
                                      uint32_t addr) {
    asm volatile("ldmatrix.sync.aligned.m8n8.x4.shared.b16 {%0,%1,%2,%3}, [%4];"
                 : "=r"(r0), "=r"(r1), "=r"(r2), "=r"(r3) : "r"(addr));
}
__device__ __forceinline__ void mma16816(float* d, uint32_t a0, uint32_t a1, uint32_t a2,
                                         uint32_t a3, uint32_t b0, uint32_t b1) {
    asm volatile("mma.sync.aligned.m16n8k16.row.col.f32.bf16.bf16.f32 "
                 "{%0,%1,%2,%3}, {%4,%5,%6,%7}, {%8,%9}, {%0,%1,%2,%3};"
                 : "+f"(d[0]), "+f"(d[1]), "+f"(d[2]), "+f"(d[3])
                 : "r"(a0), "r"(a1), "r"(a2), "r"(a3), "r"(b0), "r"(b1));
}

// ---------------- Kernel 1: prep (invert L, packed A rows, hi/lo bf16 split) ----
__device__ __forceinline__ void storeA(int ck, int p, float v) {
    __nv_bfloat16 h = __float2bfloat16(v);
    __nv_bfloat16 l = __float2bfloat16(v - __bfloat162float(h));
    const size_t base = (size_t)ck * KE;
    g_A2[base + p] = h;                 // seg0: ah   (pairs gh)
    g_A2[base + PPAD + p] = h;          // seg1: ah   (pairs gl)
    g_A2[base + 2 * PPAD + p] = l;      // seg2: al   (pairs gh)
}

__global__ void prep_kernel(const float* __restrict__ mix,
                            const float* __restrict__ loc,
                            const float* __restrict__ tril) {
    const int ck = blockIdx.x, tid = threadIdx.x;
    if (ck >= NCK) {
        const size_t base = (size_t)ck * KE;
        for (int p = tid; p < KE; p += 64) g_A2[base + p] = __float2bfloat16(0.0f);
        return;
    }
    const int c = ck >> 3, k = ck & 7;
    __shared__ float Lsh[ND][65];
    __shared__ float rowbuf[ND], locsh[ND], vsh[ND], red[ND];
    __shared__ int rs[ND + 1];

    const float* Lg = tril + (size_t)ck * ND * ND;
    for (int idx = tid; idx < ND * ND; idx += 64) Lsh[idx >> 6][idx & 63] = Lg[idx];
    locsh[tid] = loc[ck * ND + tid];
    rs[tid] = tid * ND - tid * (tid - 1) / 2;
    if (tid == 0) rs[ND] = NPAIR;
    __syncthreads();
    const float mydiag = Lsh[tid][tid];

    for (int i = 0; i < ND; ++i) {          // rows become M = L^{-1}
        rowbuf[tid] = Lsh[i][tid];
        __syncthreads();
        float nv = 0.0f;
        if (tid <= i) {
            float s = (tid == i) ? 1.0f : 0.0f;
            for (int t = tid; t < i; ++t) s -= rowbuf[t] * Lsh[t][tid];
            nv = s / rowbuf[i];
        }
        Lsh[i][tid] = nv;
        __syncthreads();
    }

    float vd = 0.0f;                        // v = M*mu
    for (int t = 0; t <= tid; ++t) vd += Lsh[tid][t] * locsh[t];
    vsh[tid] = vd;
    __syncthreads();
    float wd = 0.0f;                        // w = A*mu
    for (int t = tid; t < ND; ++t) wd += Lsh[t][tid] * vsh[t];
    storeA(ck, NPAIR + tid, -2.0f * wd);

    red[tid] = vd * vd;  __syncthreads();
    for (int o = 32; o > 0; o >>= 1) { if (tid < o) red[tid] += red[tid + o]; __syncthreads(); }
    const float cst = red[0];  __syncthreads();
    red[tid] = logf(fabsf(mydiag));  __syncthreads();
    for (int o = 32; o > 0; o >>= 1) { if (tid < o) red[tid] += red[tid + o]; __syncthreads(); }
    const float logdet = red[0];

    float ml[NK], mmx = -1e30f;
    #pragma unroll
    for (int kk = 0; kk < NK; ++kk) { ml[kk] = mix[c * NK + kk]; mmx = fmaxf(mmx, ml[kk]); }
    float msum = 0.0f;
    #pragma unroll
    for (int kk = 0; kk < NK; ++kk) msum += expf(ml[kk] - mmx);
    const float mixlog = ml[k] - (mmx + logf(msum));
    const float bias = -0.5f * cst - 32.0f * 1.8378770664093454836f - logdet + mixlog;
    if (tid == 0) storeA(ck, 2144, -2.0f * bias);
    for (int p = PDIM + tid; p < PPAD; p += 64) storeA(ck, p, 0.0f);

    int i = 0;                              // packed A = M^T M
    for (int p = tid; p < NPAIR; p += 64) {
        while (rs[i + 1] <= p) ++i;
        const int j = i + (p - rs[i]);
        float s = 0.0f;
        for (int t = j; t < ND; ++t) s += Lsh[t][i] * Lsh[t][j];
        storeA(ck, p, (i == j) ? s : 2.0f * s);
    }
}

// ---------------- Kernel 2: G rows (bf16 hi/lo, [b][k] layout) -------------
__global__ void gbuild_kernel(const float* __restrict__ rep) {
    __shared__ float xs[64 * 65];
    __shared__ int is[64], js[64];
    const int p0 = blockIdx.x * 64, b0 = blockIdx.y * 64;
    const int tid = threadIdx.x, lane = tid & 31, w = tid >> 5;

    for (int f = tid; f < 64 * 64; f += 256) {
        const int bl = f >> 6, d = f & 63;
        xs[bl * 65 + d] = rep[(size_t)(b0 + bl) * ND + d];
    }
    if (tid < 64) {
        const int p = p0 + tid;
        if (p < NPAIR) {
            int i = 0;
            while ((i + 1) * ND - (i + 1) * i / 2 <= p) ++i;
            const int rsI = i * ND - i * (i - 1) / 2;
            is[tid] = i; js[tid] = i + (p - rsI);
        } else if (p < 2144) { is[tid] = -1; js[tid] = p - NPAIR; }
        else if (p == 2144) { is[tid] = -2; js[tid] = 0; }
        else { is[tid] = -3; js[tid] = 0; }
    }
    __syncthreads();

    const int pl = 2 * lane;
    const int i0 = is[pl], j0 = js[pl], i1 = is[pl + 1], j1 = js[pl + 1];
    #pragma unroll 2
    for (int it = 0; it < 8; ++it) {
        const int bl = w + 8 * it;
        const float* xr = &xs[bl * 65];
        float v0 = (i0 >= 0) ? xr[i0] * xr[j0] : (i0 == -1 ? xr[j0] : (i0 == -2 ? 1.0f : 0.0f));
        float v1 = (i1 >= 0) ? xr[i1] * xr[j1] : (i1 == -1 ? xr[j1] : (i1 == -2 ? 1.0f : 0.0f));
        __nv_bfloat16 h0 = __float2bfloat16(v0), h1 = __float2bfloat16(v1);
        __nv_bfloat16 l0 = __float2bfloat16(v0 - __bfloat162float(h0));
        __nv_bfloat16 l1 = __float2bfloat16(v1 - __bfloat162float(h1));
        const size_t base = (size_t)(b0 + bl) * KE + p0 + pl;
        *(__nv_bfloat162*)(g_G2 + base)            = __nv_bfloat162(h0, h1);  // gh
        *(__nv_bfloat162*)(g_G2 + base + PPAD)     = __nv_bfloat162(l0, l1);  // gl
        *(__nv_bfloat162*)(g_G2 + base + 2 * PPAD) = __nv_bfloat162(h0, h1);  // gh
    }
}

// ---------------- Kernel 3: mma.sync bf16 GEMM + fused lse over k ----------
// 128 thr = 4 warps (2m x 2n); warp tile 64(m) x 32(n); block 128x64;
// 3-stage cp.async pipeline. Pending groups at top of iter s = {s, s+1}
// (s+2 load committed at end of iter), so wait_group(1) makes stage s
// resident; last iter has only {s} pending -> wait_group(0).
__global__ void __launch_bounds__(128) gemm_kernel() {
    __shared__ __align__(16) __nv_bfloat16 sA[3][BM][SROW];
    __shared__ __align__(16) __nv_bfloat16 sB[3][BN][SROW];
    const int tid = threadIdx.x, lane = tid & 31, wid = tid >> 5;
    const int wm = wid & 1, wn = wid >> 1;             // 2 x 2 warps
    const int bm0 = blockIdx.x * BM, bn0 = blockIdx.y * BN;
    const __nv_bfloat16* gA = g_G2 + (size_t)bm0 * KE;
    const __nv_bfloat16* gB = g_A2 + (size_t)bn0 * KE;
    const uint32_t sA0 = smem_u32(&sA[0][0][0]);
    const uint32_t sB0 = smem_u32(&sB[0][0][0]);
    const uint32_t ABUF = BM * SROW * 2;               // bytes per A stage
    const uint32_t BBUF = BN * SROW * 2;               // bytes per B stage

    float acc[4][4][4];                                // [mt][nt][e]
    #pragma unroll
    for (int mt = 0; mt < 4; ++mt)
        #pragma unroll
        for (int nt = 0; nt < 4; ++nt)
            #pragma unroll
            for (int e = 0; e < 4; ++e) acc[mt][nt][e] = 0.0f;

    // ldmatrix source addresses (same fragment mapping as validated R6 kernel)
    const int aRow = wm * 64 + (lane & 7) + ((lane >> 3) & 1) * 8;   // + mt*16
    const int aColB = ((lane >> 4) * 8) * 2;                         // + h*32
    const int bRow = wn * 32 + (lane & 7) + ((lane >> 4) & 1) * 8;   // + nt2*16
    const int bColB = (((lane >> 3) & 1) * 8) * 2;                   // + h*32

    #define LOAD_STAGE(s, buf) do {                                          \
        const int k0_ = (s) * KSTG;                                          \
        _Pragma("unroll")                                                    \
        for (int q = 0; q < 6; ++q) {                                        \
            const int f = tid + 128 * q;                                     \
            if (f < 512) {                                                   \
                const int r = f >> 2, cc = f & 3;                            \
                cp16(sA0 + (buf) * ABUF + r * (SROW * 2) + cc * 16,          \
                     gA + (size_t)r * KE + k0_ + cc * 8);                    \
            } else {                                                         \
                const int fb = f - 512, r = fb >> 2, cc = fb & 3;            \
                cp16(sB0 + (buf) * BBUF + r * (SROW * 2) + cc * 16,          \
                     gB + (size_t)r * KE + k0_ + cc * 8);                    \
            }                                                                \
        }                                                                    \
        CP_COMMIT();                                                         \
    } while (0)

    LOAD_STAGE(0, 0);
    LOAD_STAGE(1, 1);

    #pragma unroll 1
    for (int s = 0; s < NST; ++s) {
        const int buf = s % 3;
        if (s + 1 < NST) CP_WAIT(1);       // stage s resident, stage s+1 may pend
        else             CP_WAIT(0);       // last stage: drain all
        __syncthreads();

        const uint32_t aBase = sA0 + buf * ABUF;
        const uint32_t bBase = sB0 + buf * BBUF;
        #pragma unroll
        for (int h = 0; h < 2; ++h) {
            uint32_t a[4][4];
            #pragma unroll
            for (int mt = 0; mt < 4; ++mt)
                ldsm4(a[mt][0], a[mt][1], a[mt][2], a[mt][3],
                      aBase + (aRow + mt * 16) * (SROW * 2) + aColB + h * 32);
            uint32_t b[2][4];
            #pragma unroll
            for (int nt2 = 0; nt2 < 2; ++nt2)
                ldsm4(b[nt2][0], b[nt2][1], b[nt2][2], b[nt2][3],
                      bBase + (bRow + nt2 * 16) * (SROW * 2) + bColB + h * 32);
            #pragma unroll
            for (int mt = 0; mt < 4; ++mt)
                #pragma unroll
                for (int nt = 0; nt < 4; ++nt)
                    mma16816(acc[mt][nt], a[mt][0], a[mt][1], a[mt][2], a[mt][3],
                             b[nt >> 1][(nt & 1) * 2], b[nt >> 1][(nt & 1) * 2 + 1]);
        }
        __syncthreads();               // all reads of buf done before refill
        if (s + 2 < NST) LOAD_STAGE(s + 2, (s + 2) % 3);
    }

    // Epilogue: each n8 tile = one class (8 mixture comps). lse across the
    // 4-lane quad (each thread holds 2 cols), rows gID and gID+8.
    const int gID = lane >> 2, tig = lane & 3;
    #pragma unroll
    for (int mt = 0; mt < 4; ++mt) {
        const int row0 = bm0 + wm * 64 + mt * 16 + gID;
        #pragma unroll
        for (int nt = 0; nt < 4; ++nt) {
            const int c = bn0 / 8 + wn * 4 + nt;
            #pragma unroll
            for (int half = 0; half < 2; ++half) {
                const float v0 = -0.5f * acc[mt][nt][2 * half];
                const float v1 = -0.5f * acc[mt][nt][2 * half + 1];
                float m = fmaxf(v0, v1);
                float se = expf(v0 - m) + expf(v1 - m);
                #pragma unroll
                for (int o = 1; o <= 2; o <<= 1) {
                    const float pm = __shfl_xor_sync(0xffffffffu, m, o);
                    const float ps = __shfl_xor_sync(0xffffffffu, se, o);
                    const float M2 = fmaxf(m, pm);
                    se = se * expf(m - M2) + ps * expf(pm - M2);
                    m = M2;
                }
                if (tig == 0 && c < NC)
                    g_cls[(size_t)(row0 + 8 * half) * NC + c] = m + logf(se);
            }
        }
    }
}

// ---------------- Kernel 4: row log_softmax over C=100 ---------------------
__global__ void softmax_kernel(float* __restrict__ out) {
    const int lane = threadIdx.x & 31;
    const int b = blockIdx.x * 8 + (threadIdx.x >> 5);
    float v[4];
    float mx = -INFINITY;
    #pragma unroll
    for (int q = 0; q < 4; ++q) {
        const int cc = lane + 32 * q;
        v[q] = (cc < NC) ? g_cls[b * NC + cc] : -INFINITY;
        mx = fmaxf(mx, v[q]);
    }
    #pragma unroll
    for (int o = 16; o > 0; o >>= 1) mx = fmaxf(mx, __shfl_xor_sync(0xffffffffu, mx, o));
    float sum = 0.0f;
    #pragma unroll
    for (int q = 0; q < 4; ++q) {
        const int cc = lane + 32 * q;
        if (cc < NC) sum += expf(v[q] - mx);
    }
    #pragma unroll
    for (int o = 16; o > 0; o >>= 1) sum += __shfl_xor_sync(0xffffffffu, sum, o);
    const float lse = mx + logf(sum);
    #pragma unroll
    for (int q = 0; q < 4; ++q) {
        const int cc = lane + 32 * q;
        if (cc < NC) out[b * NC + cc] = v[q] - lse;
    }
}

extern "C" void kernel_launch(void* const* d_in, const int* in_sizes, int n_in,
                              void* d_out, int out_size) {
    const float *rep = nullptr, *mix = nullptr, *loc = nullptr, *tril = nullptr;
    for (int i = 0; i < n_in; ++i) {
        switch (in_sizes[i]) {
            case NB * ND:       rep  = (const float*)d_in[i]; break;
            case NC * NK:       mix  = (const float*)d_in[i]; break;
            case NCK * ND:      loc  = (const float*)d_in[i]; break;
            case NCK * ND * ND: tril = (const float*)d_in[i]; break;
            default: break;
        }
    }
    if (!rep || !mix || !loc || !tril) {
        rep  = (const float*)d_in[0];
        mix  = (const float*)d_in[1];
        loc  = (const float*)d_in[2];
        tril = (const float*)d_in[3];
    }
    prep_kernel<<<CK2, 64>>>(mix, loc, tril);
    gbuild_kernel<<<dim3(PPAD / 64, NB / 64), 256>>>(rep);
    gemm_kernel<<<dim3(NB / BM, CK2 / BN), 128>>>();
    softmax_kernel<<<NB / 8, 256>>>((float*)d_out);
}